// round 14
// baseline (speedup 1.0000x reference)
#include <cuda_runtime.h>

// Problem constants
#define BB 32
#define FF 64
#define LL 8192
#define KK 8
#define TT 128          // output steps per chunk
#define WW 96           // warm-up steps: alpha^96 * O(100) ~ 4e-9 abs — below fp32 noise
#define NCH (LL / TT)   // 64 chunks -> 2048 blocks
#define TILE 32         // steps buffered in smem before coalesced write-out
#define TPAD 36         // row stride: conflict-free STS.128 / LDS.128 / logits
#define XS_N (WW + TT + KK)   // 232

#define X_SCALE 20.0f
#define THR 0.25f
#define BETA 15.0f

// Streaming (evict-first) 128-bit store: output is write-once, never re-read.
__device__ __forceinline__ void stg_cs(float* p, float4 v) {
    asm volatile("st.global.cs.v4.f32 [%0], {%1, %2, %3, %4};"
                 :: "l"(p), "f"(v.x), "f"(v.y), "f"(v.z), "f"(v.w) : "memory");
}

// s = (z >= 0) ? 1.0f : 0.0f via sign bit (z is never -0.0: exact cancellation
// in fmaf yields +0.0 under round-to-nearest). SHF+LOP3, no 13-cycle FSETP.
__device__ __forceinline__ float spike_of(float z) {
    const int m = __float_as_int(z) >> 31;     // -1 if negative, 0 otherwise
    return __int_as_float(0x3F800000 & ~m);
}

// Fused conv + LIF scan + logits. Grid (B, NCH), 64 threads (one per filter).
// Round-5/13 geometry (best measured): every 128B output line is written whole
// by one 8-lane store group; all smem patterns conflict-free.
__global__ __launch_bounds__(64, 11) void snn_fused_kernel(
    const float* __restrict__ x,
    const float* __restrict__ conv_w,
    const float* __restrict__ raw_tau,
    float* __restrict__ out)
{
    __shared__ float xs[XS_N];
    __shared__ float tI[FF * TPAD];
    __shared__ float tZ[FF * TPAD];
    __shared__ float pm[TILE * 2];    // per-column partial maxes (2 warps)

    const int b = blockIdx.x;
    const int c = blockIdx.y;
    const int f = threadIdx.x;
    const int t0 = c * TT;
    const int tstart = (c == 0) ? 0 : (t0 - WW);
    const int nwarm = t0 - tstart;    // 0 or WW (multiple of 8)

    // Unit-norm filter weights (clamp 1e-8)
    float w[KK];
    float nrm = 0.0f;
#pragma unroll
    for (int k = 0; k < KK; k++) {
        w[k] = conv_w[f * KK + k];
        nrm += w[k] * w[k];
    }
    nrm = fmaxf(sqrtf(nrm), 1e-8f);
#pragma unroll
    for (int k = 0; k < KK; k++) w[k] = w[k] / nrm;

    // alpha = exp(-1 / (softplus(raw_tau) + 1e-4))
    const float rt = raw_tau[f];
    const float sp = fmaxf(rt, 0.0f) + log1pf(expf(-fabsf(rt)));
    const float alpha = expf(-1.0f / (sp + 1e-4f));
    const float oma = 1.0f - alpha;

    // Stage pre-scaled x window, zero-padded left. xs[i] = 20*x[b, tstart-7+i]
    const float* xb = x + b * LL;
    const int base = tstart - (KK - 1);
    const int total = nwarm + TT + (KK - 1);
    for (int i = f; i < total; i += FF) {
        const int g = base + i;
        xs[i] = (g >= 0) ? (X_SCALE * xb[g]) : 0.0f;
    }
    __syncthreads();

    // 8-register circular window: win[(p+k)&7] == xs[p+k]
    float win[8];
#pragma unroll
    for (int i = 0; i < 8; i++) win[i] = xs[i];

    float v = 0.0f;

    // ---- warm-up: recurrence only ----
    for (int p = 0; p < nwarm; p += 8) {
#pragma unroll
        for (int u = 0; u < 8; u++) {
            float I = 0.0f;
#pragma unroll
            for (int k = 0; k < KK; k++) I = fmaf(w[k], win[(u + k) & 7], I);
            const float vpre = fmaf(oma, I, alpha * v);
            v = (vpre >= THR) ? 0.0f : vpre;
            win[u] = xs[p + u + 8];
        }
    }

    float* const outI = out;
    float* const outZ = out + (size_t)BB * FF * LL;
    float* const outS = out + (size_t)2 * BB * FF * LL;
    float* const logits = out + (size_t)3 * BB * FF * LL;

    const int g2 = f >> 5;        // warp id (filter group of 32)
    const int cc = f & 31;        // time column 0..31

    // ---- main: TILE steps -> smem tiles -> coalesced write-out ----
    for (int jb = 0; jb < TT; jb += TILE) {
#pragma unroll
        for (int q = 0; q < TILE; q += 8) {
            float Ia[8], Za[8];
#pragma unroll
            for (int u = 0; u < 8; u++) {
                float I = 0.0f;
#pragma unroll
                for (int k = 0; k < KK; k++) I = fmaf(w[k], win[(u + k) & 7], I);
                const float vpre = fmaf(oma, I, alpha * v);
                Ia[u] = I;
                Za[u] = fmaf(BETA, vpre, -BETA * THR);
                v = (vpre >= THR) ? 0.0f : vpre;
                win[u] = xs[nwarm + jb + q + u + 8];
            }
            const int off = f * TPAD + q;
            *(float4*)&tI[off]     = make_float4(Ia[0], Ia[1], Ia[2], Ia[3]);
            *(float4*)&tI[off + 4] = make_float4(Ia[4], Ia[5], Ia[6], Ia[7]);
            *(float4*)&tZ[off]     = make_float4(Za[0], Za[1], Za[2], Za[3]);
            *(float4*)&tZ[off + 4] = make_float4(Za[4], Za[5], Za[6], Za[7]);
        }
        __syncthreads();

        const int colbase = t0 + jb;

        // Coalesced write-out: 8 consecutive lanes cover one full 128B row line.
#pragma unroll
        for (int p2 = 0; p2 < 8; p2++) {
            const int idx = p2 * 256 + f * 4;   // linear in 64x32 tile
            const int row = idx >> 5;
            const int col = idx & 31;
            const size_t g = (size_t)(b * FF + row) * LL + colbase + col;
            const int so = row * TPAD + col;
            const float4 i4 = *(const float4*)&tI[so];
            const float4 z4 = *(const float4*)&tZ[so];
            float4 s4;
            s4.x = spike_of(z4.x);
            s4.y = spike_of(z4.y);
            s4.z = spike_of(z4.z);
            s4.w = spike_of(z4.w);
            stg_cs(&outI[g], i4);
            stg_cs(&outZ[g], z4);
            stg_cs(&outS[g], s4);
        }

        // Logits partial max: warp g2 reduces its 32 filters for column cc.
        {
            float m = -3.4e38f;
#pragma unroll
            for (int ff2 = 0; ff2 < 32; ff2++)
                m = fmaxf(m, tZ[(g2 * 32 + ff2) * TPAD + cc]);
            pm[cc * 2 + g2] = m;
        }
        __syncthreads();

        // Combine the 2 warp-partials per column; 32 threads, coalesced store.
        if (f < TILE) {
            logits[b * LL + colbase + f] = fmaxf(pm[f * 2], pm[f * 2 + 1]);
        }
    }
}

extern "C" void kernel_launch(void* const* d_in, const int* in_sizes, int n_in,
                              void* d_out, int out_size)
{
    const float* x       = (const float*)d_in[0];
    const float* conv_w  = (const float*)d_in[1];
    const float* raw_tau = (const float*)d_in[2];
    float* out = (float*)d_out;

    dim3 grid(BB, NCH);
    snn_fused_kernel<<<grid, FF>>>(x, conv_w, raw_tau, out);
}

// round 15
// speedup vs baseline: 1.3129x; 1.3129x over previous
#include <cuda_runtime.h>

// Problem constants
#define BB 32
#define FF 64
#define LL 8192
#define KK 8
#define TT 128          // output steps per chunk
#define WW 128          // warm-up steps (validated rounds 2-13: rel_err ~8.7e-8)
#define NCH (LL / TT)   // 64 chunks -> 2048 blocks
#define TILE 32         // steps buffered in smem before coalesced write-out
#define TPAD 36         // row stride: conflict-free STS.128 / LDS.128 / logits
#define XS_N (WW + TT + KK)   // 264

#define X_SCALE 20.0f
#define THR 0.25f
#define BETA 15.0f

// Streaming 256-bit store (STG.256, sm_10x): halves LSU store-issue count.
__device__ __forceinline__ void stg_cs8(float* p, float4 a, float4 b) {
    asm volatile("st.global.cs.v8.f32 [%0], {%1,%2,%3,%4,%5,%6,%7,%8};"
                 :: "l"(p), "f"(a.x), "f"(a.y), "f"(a.z), "f"(a.w),
                    "f"(b.x), "f"(b.y), "f"(b.z), "f"(b.w) : "memory");
}

// Fused conv + LIF scan + logits. Grid (B, NCH), 64 threads (one per filter).
// Round-13 structure; only the write-out uses 32B stores (4 lanes per 128B
// line). s derived from z (s = z>=0, z = BETA*(vpre-THR)).
__global__ __launch_bounds__(64, 11) void snn_fused_kernel(
    const float* __restrict__ x,
    const float* __restrict__ conv_w,
    const float* __restrict__ raw_tau,
    float* __restrict__ out)
{
    __shared__ float xs[XS_N];
    __shared__ float tI[FF * TPAD];
    __shared__ float tZ[FF * TPAD];
    __shared__ float pm[TILE * 2];    // per-column partial maxes (2 warps)

    const int b = blockIdx.x;
    const int c = blockIdx.y;
    const int f = threadIdx.x;
    const int t0 = c * TT;
    const int tstart = (c == 0) ? 0 : (t0 - WW);
    const int nwarm = t0 - tstart;    // 0 or WW

    // Unit-norm filter weights (clamp 1e-8)
    float w[KK];
    float nrm = 0.0f;
#pragma unroll
    for (int k = 0; k < KK; k++) {
        w[k] = conv_w[f * KK + k];
        nrm += w[k] * w[k];
    }
    nrm = fmaxf(sqrtf(nrm), 1e-8f);
#pragma unroll
    for (int k = 0; k < KK; k++) w[k] = w[k] / nrm;

    // alpha = exp(-1 / (softplus(raw_tau) + 1e-4))
    const float rt = raw_tau[f];
    const float sp = fmaxf(rt, 0.0f) + log1pf(expf(-fabsf(rt)));
    const float alpha = expf(-1.0f / (sp + 1e-4f));
    const float oma = 1.0f - alpha;

    // Stage pre-scaled x window, zero-padded left. xs[i] = 20*x[b, tstart-7+i]
    const float* xb = x + b * LL;
    const int base = tstart - (KK - 1);
    const int total = nwarm + TT + (KK - 1);
    for (int i = f; i < total; i += FF) {
        const int g = base + i;
        xs[i] = (g >= 0) ? (X_SCALE * xb[g]) : 0.0f;
    }
    __syncthreads();

    // 8-register circular window: win[(p+k)&7] == xs[p+k]
    float win[8];
#pragma unroll
    for (int i = 0; i < 8; i++) win[i] = xs[i];

    float v = 0.0f;

    // ---- warm-up: recurrence only ----
    for (int p = 0; p < nwarm; p += 8) {
#pragma unroll
        for (int u = 0; u < 8; u++) {
            float I = 0.0f;
#pragma unroll
            for (int k = 0; k < KK; k++) I = fmaf(w[k], win[(u + k) & 7], I);
            const float vpre = fmaf(oma, I, alpha * v);
            v = (vpre >= THR) ? 0.0f : vpre;
            win[u] = xs[p + u + 8];
        }
    }

    float* const outI = out;
    float* const outZ = out + (size_t)BB * FF * LL;
    float* const outS = out + (size_t)2 * BB * FF * LL;
    float* const logits = out + (size_t)3 * BB * FF * LL;

    const int g2 = f >> 5;        // warp id (filter group of 32)
    const int cc = f & 31;        // time column 0..31

    // ---- main: TILE steps -> smem tiles -> coalesced write-out ----
    for (int jb = 0; jb < TT; jb += TILE) {
#pragma unroll
        for (int q = 0; q < TILE; q += 8) {
            float Ia[8], Za[8];
#pragma unroll
            for (int u = 0; u < 8; u++) {
                float I = 0.0f;
#pragma unroll
                for (int k = 0; k < KK; k++) I = fmaf(w[k], win[(u + k) & 7], I);
                const float vpre = fmaf(oma, I, alpha * v);
                Ia[u] = I;
                Za[u] = fmaf(BETA, vpre, -BETA * THR);
                v = (vpre >= THR) ? 0.0f : vpre;
                win[u] = xs[nwarm + jb + q + u + 8];
            }
            const int off = f * TPAD + q;
            *(float4*)&tI[off]     = make_float4(Ia[0], Ia[1], Ia[2], Ia[3]);
            *(float4*)&tI[off + 4] = make_float4(Ia[4], Ia[5], Ia[6], Ia[7]);
            *(float4*)&tZ[off]     = make_float4(Za[0], Za[1], Za[2], Za[3]);
            *(float4*)&tZ[off + 4] = make_float4(Za[4], Za[5], Za[6], Za[7]);
        }
        __syncthreads();

        const int colbase = t0 + jb;

        // Coalesced write-out with STG.256: 4 lanes cover one 128B row line.
#pragma unroll
        for (int p2 = 0; p2 < 4; p2++) {
            const int idx = p2 * 512 + f * 8;   // linear in 64x32 tile
            const int row = idx >> 5;
            const int col = idx & 31;           // 0, 8, 16, 24
            const size_t g = (size_t)(b * FF + row) * LL + colbase + col;
            const int so = row * TPAD + col;
            const float4 iA = *(const float4*)&tI[so];
            const float4 iB = *(const float4*)&tI[so + 4];
            const float4 zA = *(const float4*)&tZ[so];
            const float4 zB = *(const float4*)&tZ[so + 4];
            float4 sA, sB;
            sA.x = (zA.x >= 0.0f) ? 1.0f : 0.0f;
            sA.y = (zA.y >= 0.0f) ? 1.0f : 0.0f;
            sA.z = (zA.z >= 0.0f) ? 1.0f : 0.0f;
            sA.w = (zA.w >= 0.0f) ? 1.0f : 0.0f;
            sB.x = (zB.x >= 0.0f) ? 1.0f : 0.0f;
            sB.y = (zB.y >= 0.0f) ? 1.0f : 0.0f;
            sB.z = (zB.z >= 0.0f) ? 1.0f : 0.0f;
            sB.w = (zB.w >= 0.0f) ? 1.0f : 0.0f;
            stg_cs8(&outI[g], iA, iB);
            stg_cs8(&outZ[g], zA, zB);
            stg_cs8(&outS[g], sA, sB);
        }

        // Logits partial max: warp g2 reduces its 32 filters for column cc.
        {
            float m = -3.4e38f;
#pragma unroll
            for (int ff2 = 0; ff2 < 32; ff2++)
                m = fmaxf(m, tZ[(g2 * 32 + ff2) * TPAD + cc]);
            pm[cc * 2 + g2] = m;
        }
        __syncthreads();

        // Combine the 2 warp-partials per column; 32 threads, coalesced store.
        if (f < TILE) {
            logits[b * LL + colbase + f] = fmaxf(pm[f * 2], pm[f * 2 + 1]);
        }
    }
}

extern "C" void kernel_launch(void* const* d_in, const int* in_sizes, int n_in,
                              void* d_out, int out_size)
{
    const float* x       = (const float*)d_in[0];
    const float* conv_w  = (const float*)d_in[1];
    const float* raw_tau = (const float*)d_in[2];
    float* out = (float*)d_out;

    dim3 grid(BB, NCH);
    snn_fused_kernel<<<grid, FF>>>(x, conv_w, raw_tau, out);
}